// round 7
// baseline (speedup 1.0000x reference)
#include <cuda_runtime.h>
#include <math.h>

#define NG 192
#define BXT 32           // threads x
#define BYT 4            // threads y
#define BZT 4            // threads z
#define ZV  4            // voxels per thread along z
#define VZB (BZT * ZV)   // 16 voxels z per block
#define TX  (BXT + 4)    // 36
#define TYt (BYT + 4)    // 8
#define TZt (VZB + 4)    // 20  (u32 column stride; 80B, 16B-aligned)
#define TILE (TX * TYt * TZt)  // 5760
#define NTOT (NG * NG * NG)

#define KN   500000.0f
#define MU   0.5f
#define EPSF 1e-4f
#define FULLMASK 0xffffffffu
#define BMASK 0x00FEFEFEu

__device__ __forceinline__ int wrapN(int v) {
    if (v < 0) v += NG;
    if (v >= NG) v -= NG;
    return v;
}

// exact per-voxel evaluation + store (rare path, ~1.5% of warp-votes)
__device__ __noinline__ void exact_voxel_store(
    int ga, int gb, int gc, float two_d, float eta,
    const float* __restrict__ xg, const float* __restrict__ yg,
    const float* __restrict__ zg, const float* __restrict__ vxg,
    const float* __restrict__ vyg, const float* __restrict__ vzg,
    float* __restrict__ out)
{
    const float two_d2 = two_d * two_d;
    const int gidx = (ga * NG + gb) * NG + gc;
    const float px = xg[gidx], py = yg[gidx], pz = zg[gidx];
    const float pvx = vxg[gidx], pvy = vyg[gidx], pvz = vzg[gidx];
    float fxc = 0.f, fyc = 0.f, fzc = 0.f;
    float fxd = 0.f, fyd = 0.f, fzd = 0.f;
    float frx = 0.f, fry = 0.f, frz = 0.f;
    #pragma unroll 1
    for (int oz = -2; oz <= 2; oz++) {
        const int na = wrapN(ga + oz);
        #pragma unroll 1
        for (int oy = -2; oy <= 2; oy++) {
            const int nb = wrapN(gb + oy);
            const int rowb = (na * NG + nb) * NG;
            #pragma unroll 1
            for (int ox = -2; ox <= 2; ox++) {
                const int nc = wrapN(gc + ox);
                const int nidx = rowb + nc;
                const float dx = px - xg[nidx];
                const float dy = py - yg[nidx];
                const float dz = pz - zg[nidx];
                const float d2 = fmaf(dz, dz, fmaf(dy, dy, dx * dx));
                // d2 == 0 (incl. self) contributes exactly 0 -> skip
                const bool hit = (d2 < two_d2) && (d2 > 0.0f);
                if (hit) {
                    const float dist = sqrtf(d2);
                    const float safe = fmaxf(EPSF, dist);
                    const float inv  = 1.0f / safe;
                    const float coef = KN * (dist - two_d) * inv;
                    fxc += coef * dx;
                    fyc += coef * dy;
                    fzc += coef * dz;
                    const float dvx = pvx - vxg[nidx];
                    const float dvy = pvy - vyg[nidx];
                    const float dvz = pvz - vzg[nidx];
                    const float vn  = (dvx * dx + dvy * dy + dvz * dz) * inv;
                    const float c2  = eta * vn * inv;
                    fxd += c2 * dx;
                    fyd += c2 * dy;
                    fzd += c2 * dz;
                }
            }
        }
    }
    // friction: only the LAST scan shift s=(2,2,2) survives, i.e. neighbor
    // offset (-2,-2,-2), evaluated against the fully accumulated sums.
    {
        const int na = wrapN(ga - 2);
        const int nb = wrapN(gb - 2);
        const int nc = wrapN(gc - 2);
        const int nidx = (na * NG + nb) * NG + nc;
        const float dx = px - xg[nidx];
        const float dy = py - yg[nidx];
        const float dz = pz - zg[nidx];
        const float d2 = fmaf(dz, dz, fmaf(dy, dy, dx * dx));
        if (d2 < two_d2) {
            const float dvx = pvx - vxg[nidx];
            const float dvy = pvy - vyg[nidx];
            const float dvz = pvz - vzg[nidx];
            frx = -(fabsf(fabsf(MU * fyc) + fabsf(MU * fzc) - MU * fxd)
                    * dvx / fmaxf(EPSF, fabsf(dvx)));
            fry = -(fabsf(fabsf(MU * fxc) + fabsf(MU * fzc) - MU * fyd)
                    * dvy / fmaxf(EPSF, fabsf(dvy)));
            // NB: reference uses diffvy in the z-friction numerator (kept).
            frz = -(fabsf(fabsf(MU * fxc) + fabsf(MU * fyc) - MU * fzd)
                    * dvy / fmaxf(EPSF, fabsf(dvz)));
        }
    }
    float* o = out + gidx;
    o[0 * NTOT] = fxc;
    o[1 * NTOT] = fyc;
    o[2 * NTOT] = fzc;
    o[3 * NTOT] = fxd;
    o[4 * NTOT] = fyd;
    o[5 * NTOT] = fzd;
    o[6 * NTOT] = frx;
    o[7 * NTOT] = fry;
    o[8 * NTOT] = frz;
}

__global__ __launch_bounds__(BXT * BYT * BZT, 3)
void dem_kernel(const float* __restrict__ xg, const float* __restrict__ yg,
                const float* __restrict__ zg, const float* __restrict__ vxg,
                const float* __restrict__ vyg, const float* __restrict__ vzg,
                const float* __restrict__ dptr, float* __restrict__ out,
                float eta)
{
    // keys z-contiguous: index (ty*TX + tx)*TZt + tz ; column = 80B
    __shared__ __align__(16) unsigned qpk[TILE];

    const int lx = threadIdx.x, ly = threadIdx.y, lz = threadIdx.z;
    const int bx0 = blockIdx.x * BXT;
    const int by0 = blockIdx.y * BYT;
    const int bz0 = blockIdx.z * VZB;
    const int tid = (lz * BYT + ly) * BXT + lx;
    const int NTHR = BXT * BYT * BZT;

    // --- cooperative halo key build; gx fastest for coalesced global reads ---
    for (int idx = tid; idx < TILE; idx += NTHR) {
        int tx = idx % TX;
        int r  = idx / TX;
        int ty = r % TYt;
        int tz = r / TYt;
        int gx = wrapN(bx0 + tx - 2);
        int gy = wrapN(by0 + ty - 2);
        int gz = wrapN(bz0 + tz - 2);
        int g = (gz * NG + gy) * NG + gx;
        // coords in [0, 192): floors fit a byte
        qpk[(ty * TX + tx) * TZt + tz] =
            (unsigned)(int)xg[g] | ((unsigned)(int)yg[g] << 8)
            | ((unsigned)(int)zg[g] << 16);
    }
    __syncthreads();

    const float d     = *dptr;
    const float two_d = 2.0f * d;
    // byte-filter validity: |dx| < two_d <= 1 => |floor diff| <= 1 per axis
    const bool filter_ok = (two_d <= 1.0f);

    const int cx = lx + 2, cyy = ly + 2;
    const int ccol = (cyy * TX + cx) * TZt;
    // 4 centers at tz = 2 + 4*lz + c
    const unsigned pq0 = qpk[ccol + 2 + 4 * lz + 0];
    const unsigned pq1 = qpk[ccol + 2 + 4 * lz + 1];
    const unsigned pq2 = qpk[ccol + 2 + 4 * lz + 2];
    const unsigned pq3 = qpk[ccol + 2 + 4 * lz + 3];

    const int gy = by0 + ly, gx = bx0 + lx;

    // ---- byte prefilter over 25 (oy,ox) columns; 2x LDS.128 each ----
    unsigned m0 = ~0u, m1 = ~0u, m2 = ~0u, m3 = ~0u;
    if (filter_ok) {
        const uint4* qpk4 = (const uint4*)qpk;
        #pragma unroll
        for (int oy = -2; oy <= 2; oy++) {
            #pragma unroll
            for (int ox = -2; ox <= 2; ox++) {
                const int col = (cyy + oy) * TX + (cx + ox);
                const int b4  = col * (TZt / 4) + lz;   // strip starts tz=4*lz
                const uint4 A = qpk4[b4];
                const uint4 B = qpk4[b4 + 1];
                const unsigned k0 = A.x, k1 = A.y, k2 = A.z, k3 = A.w;
                const unsigned k4 = B.x, k5 = B.y, k6 = B.z, k7 = B.w;
                const bool selfcol = (oy == 0) && (ox == 0);
                // center c tests strip keys j = c .. c+4 ; self at j = c+2
                #define TST(M, P, K) M = min(M, __vabsdiffu4(P, K) & BMASK)
                TST(m0, pq0, k0); TST(m0, pq0, k1);
                if (!selfcol) TST(m0, pq0, k2);
                TST(m0, pq0, k3); TST(m0, pq0, k4);
                TST(m1, pq1, k1); TST(m1, pq1, k2);
                if (!selfcol) TST(m1, pq1, k3);
                TST(m1, pq1, k4); TST(m1, pq1, k5);
                TST(m2, pq2, k2); TST(m2, pq2, k3);
                if (!selfcol) TST(m2, pq2, k4);
                TST(m2, pq2, k5); TST(m2, pq2, k6);
                TST(m3, pq3, k3); TST(m3, pq3, k4);
                if (!selfcol) TST(m3, pq3, k5);
                TST(m3, pq3, k6); TST(m3, pq3, k7);
                #undef TST
            }
        }
    }

    // ---- per-center vote, rare exact path, or zero stores ----
    #pragma unroll
    for (int c = 0; c < 4; c++) {
        const unsigned mc = (c == 0) ? m0 : (c == 1) ? m1 : (c == 2) ? m2 : m3;
        const bool need = !filter_ok || (mc == 0u);
        const int gzc = bz0 + 4 * lz + c;
        const int gidx = (gzc * NG + gy) * NG + gx;
        bool done = false;
        if (__any_sync(FULLMASK, need)) {
            if (need) {
                exact_voxel_store(gzc, gy, gx, two_d, eta,
                                  xg, yg, zg, vxg, vyg, vzg, out);
                done = true;
            }
        }
        if (!done) {
            float* o = out + gidx;
            o[0 * NTOT] = 0.f;
            o[1 * NTOT] = 0.f;
            o[2 * NTOT] = 0.f;
            o[3 * NTOT] = 0.f;
            o[4 * NTOT] = 0.f;
            o[5 * NTOT] = 0.f;
            o[6 * NTOT] = 0.f;
            o[7 * NTOT] = 0.f;
            o[8 * NTOT] = 0.f;
        }
    }
}

extern "C" void kernel_launch(void* const* d_in, const int* in_sizes, int n_in,
                              void* d_out, int out_size)
{
    const float* xg   = (const float*)d_in[0];
    const float* yg   = (const float*)d_in[1];
    const float* zg   = (const float*)d_in[2];
    const float* vxg  = (const float*)d_in[3];
    const float* vyg  = (const float*)d_in[4];
    const float* vzg  = (const float*)d_in[5];
    const float* dptr = (const float*)d_in[6];
    float* out = (float*)d_out;

    // ETA = 2*gamma*sqrt(KN), gamma = alpha/sqrt(alpha^2+1), alpha = -ln(0.7)/pi
    const double alpha = -log(0.7) / M_PI;
    const double gam   = alpha / sqrt(alpha * alpha + 1.0);
    const float  eta   = (float)(2.0 * gam * sqrt(500000.0));

    dim3 block(BXT, BYT, BZT);
    dim3 grid(NG / BXT, NG / BYT, NG / VZB);
    dem_kernel<<<grid, block>>>(xg, yg, zg, vxg, vyg, vzg, dptr, out, eta);
}